// round 12
// baseline (speedup 1.0000x reference)
#include <cuda_runtime.h>

#define Bc 64
#define Tc 2000
#define Lc 400
#define Mc 80
#define EPSc 1e-8f
#define LN2f 0.69314718055994531f
// sqrt(0.5 * log2(e)) — so that 2^{-((l-ep)*K2)^2} = e^{-z^2/2}, K2=SQHL2E/sigma
#define SQHL2E 0.84932180028801905f

// accumulators: 0=s1(mel1), 1=s2(mel2), 2=gate, 3=kl_sum, 4=ent_sum(Σ p*logp)
// Zero at module load; the last block re-zeros after finalizing (replay-safe).
__device__ double g_acc[5];
__device__ unsigned int g_ticket;

__device__ __forceinline__ float fast_lg2(float x) {
    float r;
    asm("lg2.approx.f32 %0, %1;" : "=f"(r) : "f"(x));
    return r;
}
__device__ __forceinline__ float fast_ex2(float x) {
    float r;
    asm("ex2.approx.f32 %0, %1;" : "=f"(r) : "f"(x));
    return r;
}

__device__ __forceinline__ float warp_sum(float v) {
    v += __shfl_xor_sync(0xffffffffu, v, 16);
    v += __shfl_xor_sync(0xffffffffu, v, 8);
    v += __shfl_xor_sync(0xffffffffu, v, 4);
    v += __shfl_xor_sync(0xffffffffu, v, 2);
    v += __shfl_xor_sync(0xffffffffu, v, 1);
    return v;
}

// ---------------- attn: 4 rows per warp, 8 lanes per row, pipelined --------
__device__ __forceinline__ void attn_work(int aid, const float4* __restrict__ attn,
                                          const int* __restrict__ text_len,
                                          float* sred) {
    int lane = threadIdx.x & 31, wid = threadIdx.x >> 5;
    int lig = lane & 7;           // lane in 8-lane group
    int grp = lane >> 3;          // group 0..3
    int rowid = (aid * 8 + wid) * 4 + grp;          // [0, 128000)
    int b = (int)((unsigned)rowid / (unsigned)Tc);
    int t = rowid - b * Tc;

    int Lb = __ldg(&text_len[b]);
    float sigma = fminf(fmaxf((float)Lb * 0.05f, 3.0f), 10.0f);
    int ep_i = (t * Lb) / Tc;
    if (ep_i > Lb - 1) ep_i = Lb - 1;
    float ep = (float)ep_i;
    float K2 = SQHL2E / sigma;
    int band_lo = ep_i - 67, band_hi = ep_i + 67;

    const float4* row = attn + rowid * (Lc / 4);

    float E2 = 0.f, sg = 0.f, A2 = 0.f;
    float4 nxt = row[lig];                 // prefetch it=0
#pragma unroll
    for (int it = 0; it < 13; it++) {
        float4 a4 = nxt;
        if (it < 11) {
            nxt = row[(it + 1) * 8 + lig];
        } else if (it == 11) {
            nxt = (lig < 4) ? row[96 + lig] : make_float4(1.f, 1.f, 1.f, 1.f);
        }
        if (it == 12 && lig >= 4) a4 = make_float4(1.f, 1.f, 1.f, 1.f);

        float a0 = fmaxf(a4.x, EPSc);
        float a1 = fmaxf(a4.y, EPSc);
        float a2 = fmaxf(a4.z, EPSc);
        float a3 = fmaxf(a4.w, EPSc);
        float p0 = fast_lg2(a0);
        float p1 = fast_lg2(a1);
        float p2 = fast_lg2(a2);
        float p3 = fast_lg2(a3);
        E2 += a0 * p0;
        E2 += a1 * p1;
        E2 += a2 * p2;
        E2 += a3 * p3;

        int seg_lo = it * 32;              // l range of this iteration per group
        bool inband = (seg_lo <= band_hi) && (seg_lo + 31 >= band_lo);
        if (__any_sync(0xffffffffu, inband)) {
            int j = it * 8 + lig;
            int l0 = j * 4;
            bool jv = (it < 12) || (lig < 4);
            float u0 = ((float)l0 - ep) * K2;
            float u1 = u0 + K2;
            float u2 = u1 + K2;
            float u3 = u2 + K2;
            float h0 = -u0 * u0;
            float h1 = -u1 * u1;
            float h2 = -u2 * u2;
            float h3 = -u3 * u3;
            bool m = inband & jv;
            float g0 = (m && l0 + 0 < Lb) ? fast_ex2(h0) : 0.f;
            float g1 = (m && l0 + 1 < Lb) ? fast_ex2(h1) : 0.f;
            float g2 = (m && l0 + 2 < Lb) ? fast_ex2(h2) : 0.f;
            float g3 = (m && l0 + 3 < Lb) ? fast_ex2(h3) : 0.f;
            sg += (g0 + g1) + (g2 + g3);
            A2 += g0 * (h0 - p0);
            A2 += g1 * (h1 - p1);
            A2 += g2 * (h2 - p2);
            A2 += g3 * (h3 - p3);
        }
    }

    // row reduction within each 8-lane group (3 steps serve all 4 rows)
    sg += __shfl_xor_sync(0xffffffffu, sg, 1);
    sg += __shfl_xor_sync(0xffffffffu, sg, 2);
    sg += __shfl_xor_sync(0xffffffffu, sg, 4);
    A2 += __shfl_xor_sync(0xffffffffu, A2, 1);
    A2 += __shfl_xor_sync(0xffffffffu, A2, 2);
    A2 += __shfl_xor_sync(0xffffffffu, A2, 4);
    E2 += __shfl_xor_sync(0xffffffffu, E2, 1);
    E2 += __shfl_xor_sync(0xffffffffu, E2, 2);
    E2 += __shfl_xor_sync(0xffffffffu, E2, 4);

    float kl = 0.f, en = 0.f;
    if (lig == 0) {
        float S = sg + EPSc;
        float lnS = LN2f * fast_lg2(S);
        kl = (LN2f * A2 - sg * lnS) / S;
        en = LN2f * E2;
    }
    kl += __shfl_xor_sync(0xffffffffu, kl, 8);
    kl += __shfl_xor_sync(0xffffffffu, kl, 16);
    en += __shfl_xor_sync(0xffffffffu, en, 8);
    en += __shfl_xor_sync(0xffffffffu, en, 16);

    if (lane == 0) { sred[wid] = kl; sred[8 + wid] = en; }
    __syncthreads();
    if (wid == 0) {
        float k = (lane < 8) ? sred[lane] : 0.f;
        float e = (lane < 8) ? sred[8 + lane] : 0.f;
        k = warp_sum(k);
        e = warp_sum(e);
        if (lane == 0) {
            atomicAdd(&g_acc[3], (double)k);
            atomicAdd(&g_acc[4], (double)e);
        }
    }
}

// ---------------- mel L1 losses (4x unrolled grid-stride) ------------------
#define N_MEL 1200

__device__ __forceinline__ void mel_work(int mid,
                                         const float4* __restrict__ post,
                                         const float4* __restrict__ out,
                                         const float4* __restrict__ tgt,
                                         const int* __restrict__ mel_len,
                                         float* sred) {
    const int n4 = Bc * Tc * Mc / 4;  // 2,048,000
    const int stride = N_MEL * 256;
    float s1 = 0.f, s2 = 0.f;
    for (int i = mid * 256 + threadIdx.x; i < n4; i += 4 * stride) {
#pragma unroll
        for (int k = 0; k < 4; k++) {
            int idx = i + k * stride;
            if (idx < n4) {
                int rowi = idx / (Mc / 4);
                int b = rowi / Tc;
                int t = rowi - b * Tc;
                if (t < __ldg(&mel_len[b])) {
                    float4 o = out[idx], p = post[idx], g = tgt[idx];
                    s1 += (fabsf(o.x - g.x) + fabsf(o.y - g.y)) + (fabsf(o.z - g.z) + fabsf(o.w - g.w));
                    s2 += (fabsf(p.x - g.x) + fabsf(p.y - g.y)) + (fabsf(p.z - g.z) + fabsf(p.w - g.w));
                }
            }
        }
    }
    int lane = threadIdx.x & 31, wid = threadIdx.x >> 5;
    s1 = warp_sum(s1);
    s2 = warp_sum(s2);
    if (lane == 0) { sred[wid] = s1; sred[8 + wid] = s2; }
    __syncthreads();
    if (wid == 0) {
        float a = (lane < 8) ? sred[lane] : 0.f;
        float c = (lane < 8) ? sred[8 + lane] : 0.f;
        a = warp_sum(a);
        c = warp_sum(c);
        if (lane == 0) {
            atomicAdd(&g_acc[0], (double)a);
            atomicAdd(&g_acc[1], (double)c);
        }
    }
}

// ---------------- gate BCE-with-logits -------------------------------------
#define N_GATE 32

__device__ __forceinline__ void gate_work(int gid,
                                          const float* __restrict__ x,
                                          const float* __restrict__ z,
                                          float* sred) {
    const int n = Bc * Tc;
    int stride = N_GATE * 256;
    float s = 0.f;
    for (int i = gid * 256 + threadIdx.x; i < n; i += stride) {
        float xi = x[i], zi = z[i];
        s += fmaxf(xi, 0.f) - xi * zi + log1pf(__expf(-fabsf(xi)));
    }
    int lane = threadIdx.x & 31, wid = threadIdx.x >> 5;
    s = warp_sum(s);
    if (lane == 0) sred[wid] = s;
    __syncthreads();
    if (wid == 0) {
        float a = (lane < 8) ? sred[lane] : 0.f;
        a = warp_sum(a);
        if (lane == 0) atomicAdd(&g_acc[2], (double)a);
    }
}

// ---------------- fused kernel + last-block finalize ------------------------
// bid < 5200:  q=bid/13, r=bid%13;  r<10 -> attn id q*10+r  ([0,4000))
//                                   r>=10 -> mel id q*3+(r-10) ([0,1200))
// bid >= 5200: gate block ([0,32))
#define GRID_TOTAL (5200 + N_GATE)

__global__ void __launch_bounds__(256)
fused_kernel(const float4* __restrict__ post,
             const float4* __restrict__ out,
             const float*  __restrict__ gate_x,
             const float4* __restrict__ attn,
             const float4* __restrict__ tgt,
             const float*  __restrict__ gate_z,
             const int* __restrict__ mel_len,
             const int* __restrict__ text_len,
             float* __restrict__ outp) {
    __shared__ float sred[16];
    int bid = blockIdx.x;
    if (bid >= 5200) {
        gate_work(bid - 5200, gate_x, gate_z, sred);
    } else {
        int q = bid / 13;
        int r = bid - 13 * q;
        if (r < 10) {
            attn_work(q * 10 + r, attn, text_len, sred);
        } else {
            mel_work(q * 3 + (r - 10), post, out, tgt, mel_len, sred);
        }
    }

    // ---- last-block finalize (thread 0 of each block holds the ticket) ----
    if (threadIdx.x == 0) {
        __threadfence();                       // publish this block's g_acc adds
        unsigned tk = atomicAdd(&g_ticket, 1u);
        if (tk == GRID_TOTAL - 1) {            // I am the last block
            __threadfence();                   // acquire all other blocks' adds

            volatile double* acc = g_acc;
            double a0 = acc[0], a1 = acc[1], a2v = acc[2], a3v = acc[3], a4v = acc[4];

            double nvalid = 0.0;
            for (int b = 0; b < Bc; b++) nvalid += (double)__ldg(&mel_len[b]);
            nvalid *= (double)Mc;

            double loss_mel = (a0 + a1) / nvalid;
            double loss_gate = a2v / (double)(Bc * Tc);
            double kl = a3v / (double)Bc / (double)Tc;
            if (kl > 150.0) kl = 150.0;
            double ent = -a4v / (double)(Bc * Tc);
            double ratio = ent / 3.5;
            if (ratio < 0.0) ratio = 0.0;
            double w;
            if (ent <= 3.5) {
                w = ratio > 0.2 ? ratio : 0.2;
            } else {
                w = 1.0;
            }
            double total = loss_mel + loss_gate + w * kl;
            outp[0] = (float)total;
            outp[1] = (float)loss_mel;
            outp[2] = (float)loss_gate;
            outp[3] = (float)kl;

            // reset state for the next (replayed) invocation
            acc[0] = 0.0; acc[1] = 0.0; acc[2] = 0.0; acc[3] = 0.0; acc[4] = 0.0;
            __threadfence();
            atomicExch(&g_ticket, 0u);
        }
    }
}

extern "C" void kernel_launch(void* const* d_in, const int* in_sizes, int n_in,
                              void* d_out, int out_size) {
    const float* mel_out_postnet = (const float*)d_in[0];
    const float* mel_out         = (const float*)d_in[1];
    const float* gate_out        = (const float*)d_in[2];
    const float* alignments      = (const float*)d_in[3];
    const float* mel_target      = (const float*)d_in[4];
    const float* gate_target     = (const float*)d_in[5];
    const int*   mel_lengths     = (const int*)d_in[6];
    const int*   text_lengths    = (const int*)d_in[7];
    float* outp = (float*)d_out;

    fused_kernel<<<GRID_TOTAL, 256>>>((const float4*)mel_out_postnet,
                                      (const float4*)mel_out,
                                      gate_out,
                                      (const float4*)alignments,
                                      (const float4*)mel_target,
                                      gate_target,
                                      mel_lengths, text_lengths, outp);
    (void)in_sizes; (void)n_in; (void)out_size;
}

// round 14
// speedup vs baseline: 1.1015x; 1.1015x over previous
#include <cuda_runtime.h>

#define Bc 64
#define Tc 2000
#define Lc 400
#define Mc 80
#define EPSc 1e-8f
#define LN2f 0.69314718055994531f
// sqrt(0.5 * log2(e)) — so that 2^{-((l-ep)*K2)^2} = e^{-z^2/2}, K2=SQHL2E/sigma
#define SQHL2E 0.84932180028801905f

// accumulators: 0=s1(mel1), 1=s2(mel2), 2=gate, 3=kl_sum, 4=ent_sum(Σ p*logp)
// Zero at module load; final_kernel re-zeros after use (graph-replay safe).
__device__ double g_acc[5];

__device__ __forceinline__ float fast_lg2(float x) {
    float r;
    asm("lg2.approx.f32 %0, %1;" : "=f"(r) : "f"(x));
    return r;
}
__device__ __forceinline__ float fast_ex2(float x) {
    float r;
    asm("ex2.approx.f32 %0, %1;" : "=f"(r) : "f"(x));
    return r;
}

__device__ __forceinline__ float warp_sum(float v) {
    v += __shfl_xor_sync(0xffffffffu, v, 16);
    v += __shfl_xor_sync(0xffffffffu, v, 8);
    v += __shfl_xor_sync(0xffffffffu, v, 4);
    v += __shfl_xor_sync(0xffffffffu, v, 2);
    v += __shfl_xor_sync(0xffffffffu, v, 1);
    return v;
}

// ---------------- attn: 4 rows per warp, 8 lanes per row, pipelined --------
__device__ __forceinline__ void attn_work(int aid, const float4* __restrict__ attn,
                                          const int* __restrict__ text_len,
                                          float* sred) {
    int lane = threadIdx.x & 31, wid = threadIdx.x >> 5;
    int lig = lane & 7;           // lane in 8-lane group
    int grp = lane >> 3;          // group 0..3
    int rowid = (aid * 8 + wid) * 4 + grp;          // [0, 128000)
    int b = (int)((unsigned)rowid / (unsigned)Tc);
    int t = rowid - b * Tc;

    int Lb = __ldg(&text_len[b]);
    float sigma = fminf(fmaxf((float)Lb * 0.05f, 3.0f), 10.0f);
    int ep_i = (t * Lb) / Tc;
    if (ep_i > Lb - 1) ep_i = Lb - 1;
    float ep = (float)ep_i;
    float K2 = SQHL2E / sigma;
    int band_lo = ep_i - 67, band_hi = ep_i + 67;

    const float4* row = attn + rowid * (Lc / 4);

    float E2 = 0.f, sg = 0.f, A2 = 0.f;
    float4 nxt = __ldcs(row + lig);        // prefetch it=0 (streaming, evict-first)
#pragma unroll
    for (int it = 0; it < 13; it++) {
        float4 a4 = nxt;
        if (it < 11) {
            nxt = __ldcs(row + (it + 1) * 8 + lig);
        } else if (it == 11) {
            nxt = (lig < 4) ? __ldcs(row + 96 + lig) : make_float4(1.f, 1.f, 1.f, 1.f);
        }
        if (it == 12 && lig >= 4) a4 = make_float4(1.f, 1.f, 1.f, 1.f);

        float a0 = fmaxf(a4.x, EPSc);
        float a1 = fmaxf(a4.y, EPSc);
        float a2 = fmaxf(a4.z, EPSc);
        float a3 = fmaxf(a4.w, EPSc);
        float p0 = fast_lg2(a0);
        float p1 = fast_lg2(a1);
        float p2 = fast_lg2(a2);
        float p3 = fast_lg2(a3);
        E2 += a0 * p0;
        E2 += a1 * p1;
        E2 += a2 * p2;
        E2 += a3 * p3;

        int seg_lo = it * 32;              // l range of this iteration per group
        bool inband = (seg_lo <= band_hi) && (seg_lo + 31 >= band_lo);
        if (__any_sync(0xffffffffu, inband)) {
            int j = it * 8 + lig;
            int l0 = j * 4;
            bool jv = (it < 12) || (lig < 4);
            float u0 = ((float)l0 - ep) * K2;
            float u1 = u0 + K2;
            float u2 = u1 + K2;
            float u3 = u2 + K2;
            float h0 = -u0 * u0;
            float h1 = -u1 * u1;
            float h2 = -u2 * u2;
            float h3 = -u3 * u3;
            bool m = inband & jv;
            float g0 = (m && l0 + 0 < Lb) ? fast_ex2(h0) : 0.f;
            float g1 = (m && l0 + 1 < Lb) ? fast_ex2(h1) : 0.f;
            float g2 = (m && l0 + 2 < Lb) ? fast_ex2(h2) : 0.f;
            float g3 = (m && l0 + 3 < Lb) ? fast_ex2(h3) : 0.f;
            sg += (g0 + g1) + (g2 + g3);
            A2 += g0 * (h0 - p0);
            A2 += g1 * (h1 - p1);
            A2 += g2 * (h2 - p2);
            A2 += g3 * (h3 - p3);
        }
    }

    // row reduction within each 8-lane group (3 steps serve all 4 rows)
    sg += __shfl_xor_sync(0xffffffffu, sg, 1);
    sg += __shfl_xor_sync(0xffffffffu, sg, 2);
    sg += __shfl_xor_sync(0xffffffffu, sg, 4);
    A2 += __shfl_xor_sync(0xffffffffu, A2, 1);
    A2 += __shfl_xor_sync(0xffffffffu, A2, 2);
    A2 += __shfl_xor_sync(0xffffffffu, A2, 4);
    E2 += __shfl_xor_sync(0xffffffffu, E2, 1);
    E2 += __shfl_xor_sync(0xffffffffu, E2, 2);
    E2 += __shfl_xor_sync(0xffffffffu, E2, 4);

    float kl = 0.f, en = 0.f;
    if (lig == 0) {
        float S = sg + EPSc;
        float lnS = LN2f * fast_lg2(S);
        kl = (LN2f * A2 - sg * lnS) / S;
        en = LN2f * E2;
    }
    kl += __shfl_xor_sync(0xffffffffu, kl, 8);
    kl += __shfl_xor_sync(0xffffffffu, kl, 16);
    en += __shfl_xor_sync(0xffffffffu, en, 8);
    en += __shfl_xor_sync(0xffffffffu, en, 16);

    if (lane == 0) { sred[wid] = kl; sred[8 + wid] = en; }
    __syncthreads();
    if (wid == 0) {
        float k = (lane < 8) ? sred[lane] : 0.f;
        float e = (lane < 8) ? sred[8 + lane] : 0.f;
        k = warp_sum(k);
        e = warp_sum(e);
        if (lane == 0) {
            atomicAdd(&g_acc[3], (double)k);
            atomicAdd(&g_acc[4], (double)e);
        }
    }
}

// ---------------- mel L1 losses (4x unrolled grid-stride, streaming) -------
#define N_MEL 1200

__device__ __forceinline__ void mel_work(int mid,
                                         const float4* __restrict__ post,
                                         const float4* __restrict__ out,
                                         const float4* __restrict__ tgt,
                                         const int* __restrict__ mel_len,
                                         float* sred) {
    const int n4 = Bc * Tc * Mc / 4;  // 2,048,000
    const int stride = N_MEL * 256;
    float s1 = 0.f, s2 = 0.f;
    for (int i = mid * 256 + threadIdx.x; i < n4; i += 4 * stride) {
#pragma unroll
        for (int k = 0; k < 4; k++) {
            int idx = i + k * stride;
            if (idx < n4) {
                int rowi = idx / (Mc / 4);
                int b = rowi / Tc;
                int t = rowi - b * Tc;
                if (t < __ldg(&mel_len[b])) {
                    float4 o = __ldcs(out + idx);
                    float4 p = __ldcs(post + idx);
                    float4 g = __ldcs(tgt + idx);
                    s1 += (fabsf(o.x - g.x) + fabsf(o.y - g.y)) + (fabsf(o.z - g.z) + fabsf(o.w - g.w));
                    s2 += (fabsf(p.x - g.x) + fabsf(p.y - g.y)) + (fabsf(p.z - g.z) + fabsf(p.w - g.w));
                }
            }
        }
    }
    int lane = threadIdx.x & 31, wid = threadIdx.x >> 5;
    s1 = warp_sum(s1);
    s2 = warp_sum(s2);
    if (lane == 0) { sred[wid] = s1; sred[8 + wid] = s2; }
    __syncthreads();
    if (wid == 0) {
        float a = (lane < 8) ? sred[lane] : 0.f;
        float c = (lane < 8) ? sred[8 + lane] : 0.f;
        a = warp_sum(a);
        c = warp_sum(c);
        if (lane == 0) {
            atomicAdd(&g_acc[0], (double)a);
            atomicAdd(&g_acc[1], (double)c);
        }
    }
}

// ---------------- gate BCE-with-logits -------------------------------------
#define N_GATE 32

__device__ __forceinline__ void gate_work(int gid,
                                          const float* __restrict__ x,
                                          const float* __restrict__ z,
                                          float* sred) {
    const int n = Bc * Tc;
    int stride = N_GATE * 256;
    float s = 0.f;
    for (int i = gid * 256 + threadIdx.x; i < n; i += stride) {
        float xi = __ldcs(x + i), zi = __ldcs(z + i);
        s += fmaxf(xi, 0.f) - xi * zi + log1pf(__expf(-fabsf(xi)));
    }
    int lane = threadIdx.x & 31, wid = threadIdx.x >> 5;
    s = warp_sum(s);
    if (lane == 0) sred[wid] = s;
    __syncthreads();
    if (wid == 0) {
        float a = (lane < 8) ? sred[lane] : 0.f;
        a = warp_sum(a);
        if (lane == 0) atomicAdd(&g_acc[2], (double)a);
    }
}

// ---------------- fused kernel ---------------------------------------------
// bid < 5200:  q=bid/13, r=bid%13;  r<10 -> attn id q*10+r  ([0,4000))
//                                   r>=10 -> mel id q*3+(r-10) ([0,1200))
// bid >= 5200: gate block ([0,32))
#define GRID_TOTAL (5200 + N_GATE)

__global__ void __launch_bounds__(256)
fused_kernel(const float4* __restrict__ post,
             const float4* __restrict__ out,
             const float*  __restrict__ gate_x,
             const float4* __restrict__ attn,
             const float4* __restrict__ tgt,
             const float*  __restrict__ gate_z,
             const int* __restrict__ mel_len,
             const int* __restrict__ text_len) {
    __shared__ float sred[16];
    int bid = blockIdx.x;
    if (bid >= 5200) {
        gate_work(bid - 5200, gate_x, gate_z, sred);
        return;
    }
    int q = bid / 13;
    int r = bid - 13 * q;
    if (r < 10) {
        attn_work(q * 10 + r, attn, text_len, sred);
    } else {
        mel_work(q * 3 + (r - 10), post, out, tgt, mel_len, sred);
    }
}

// ---------------- finalize (one warp, parallel mel_len sum) ----------------
__global__ void final_kernel(const int* __restrict__ mel_len,
                             float* __restrict__ outp) {
    int lane = threadIdx.x & 31;
    // parallel sum of mel_len (64 ints over 32 lanes)
    int ml = __ldg(&mel_len[lane]) + __ldg(&mel_len[lane + 32]);
    ml += __shfl_xor_sync(0xffffffffu, ml, 16);
    ml += __shfl_xor_sync(0xffffffffu, ml, 8);
    ml += __shfl_xor_sync(0xffffffffu, ml, 4);
    ml += __shfl_xor_sync(0xffffffffu, ml, 2);
    ml += __shfl_xor_sync(0xffffffffu, ml, 1);

    if (lane == 0) {
        double nvalid = (double)ml * (double)Mc;

        double loss_mel = (g_acc[0] + g_acc[1]) / nvalid;
        double loss_gate = g_acc[2] / (double)(Bc * Tc);
        double kl = g_acc[3] / (double)Bc / (double)Tc;
        if (kl > 150.0) kl = 150.0;
        double ent = -g_acc[4] / (double)(Bc * Tc);
        double ratio = ent / 3.5;
        if (ratio < 0.0) ratio = 0.0;
        double w;
        if (ent <= 3.5) {
            w = ratio > 0.2 ? ratio : 0.2;
        } else {
            w = 1.0;
        }
        double total = loss_mel + loss_gate + w * kl;
        outp[0] = (float)total;
        outp[1] = (float)loss_mel;
        outp[2] = (float)loss_gate;
        outp[3] = (float)kl;

        // reset for the next (replayed) invocation
        g_acc[0] = 0.0; g_acc[1] = 0.0; g_acc[2] = 0.0;
        g_acc[3] = 0.0; g_acc[4] = 0.0;
    }
}

extern "C" void kernel_launch(void* const* d_in, const int* in_sizes, int n_in,
                              void* d_out, int out_size) {
    const float* mel_out_postnet = (const float*)d_in[0];
    const float* mel_out         = (const float*)d_in[1];
    const float* gate_out        = (const float*)d_in[2];
    const float* alignments      = (const float*)d_in[3];
    const float* mel_target      = (const float*)d_in[4];
    const float* gate_target     = (const float*)d_in[5];
    const int*   mel_lengths     = (const int*)d_in[6];
    const int*   text_lengths    = (const int*)d_in[7];
    float* outp = (float*)d_out;

    fused_kernel<<<GRID_TOTAL, 256>>>((const float4*)mel_out_postnet,
                                      (const float4*)mel_out,
                                      gate_out,
                                      (const float4*)alignments,
                                      (const float4*)mel_target,
                                      gate_target,
                                      mel_lengths, text_lengths);
    final_kernel<<<1, 32>>>(mel_lengths, outp);
    (void)in_sizes; (void)n_in; (void)out_size;
}

// round 15
// speedup vs baseline: 1.1199x; 1.0167x over previous
#include <cuda_runtime.h>

#define Bc 64
#define Tc 2000
#define Lc 400
#define Mc 80
#define EPSc 1e-8f
#define LN2f 0.69314718055994531f
// sqrt(0.5 * log2(e)) — so that 2^{-((l-ep)*K2)^2} = e^{-z^2/2}, K2=SQHL2E/sigma
#define SQHL2E 0.84932180028801905f

// accumulators: 0=s1(mel1), 1=s2(mel2), 2=gate, 3=kl_sum, 4=ent_sum(Σ p*logp)
// Zero at module load; final_kernel re-zeros after use (graph-replay safe).
__device__ double g_acc[5];

__device__ __forceinline__ float fast_lg2(float x) {
    float r;
    asm("lg2.approx.f32 %0, %1;" : "=f"(r) : "f"(x));
    return r;
}
__device__ __forceinline__ float fast_ex2(float x) {
    float r;
    asm("ex2.approx.f32 %0, %1;" : "=f"(r) : "f"(x));
    return r;
}

__device__ __forceinline__ float warp_sum(float v) {
    v += __shfl_xor_sync(0xffffffffu, v, 16);
    v += __shfl_xor_sync(0xffffffffu, v, 8);
    v += __shfl_xor_sync(0xffffffffu, v, 4);
    v += __shfl_xor_sync(0xffffffffu, v, 2);
    v += __shfl_xor_sync(0xffffffffu, v, 1);
    return v;
}

// ---------------- attn: 4 rows per warp, 8 lanes per row, depth-2 pipeline -
__device__ __forceinline__ void attn_work(int aid, const float4* __restrict__ attn,
                                          const int* __restrict__ text_len,
                                          float* sred) {
    int lane = threadIdx.x & 31, wid = threadIdx.x >> 5;
    int lig = lane & 7;           // lane in 8-lane group
    int grp = lane >> 3;          // group 0..3
    int rowid = (aid * 8 + wid) * 4 + grp;          // [0, 128000)
    int b = (int)((unsigned)rowid / (unsigned)Tc);
    int t = rowid - b * Tc;

    int Lb = __ldg(&text_len[b]);
    float sigma = fminf(fmaxf((float)Lb * 0.05f, 3.0f), 10.0f);
    int ep_i = (t * Lb) / Tc;
    if (ep_i > Lb - 1) ep_i = Lb - 1;
    float ep = (float)ep_i;
    float K2 = SQHL2E / sigma;
    int band_lo = ep_i - 67, band_hi = ep_i + 67;

    const float4* row = attn + rowid * (Lc / 4);

    float E2 = 0.f, sg = 0.f, A2 = 0.f;
    // depth-2 register double-buffer (evict-first streaming loads)
    float4 buf0 = __ldcs(row + lig);          // it=0
    float4 buf1 = __ldcs(row + 8 + lig);      // it=1
#pragma unroll
    for (int it = 0; it < 13; it++) {
        float4 a4 = (it & 1) ? buf1 : buf0;
        // prefetch it+2
        if (it + 2 <= 11) {
            float4 nv = __ldcs(row + (it + 2) * 8 + lig);
            if (it & 1) buf1 = nv; else buf0 = nv;
        } else if (it + 2 == 12) {
            float4 nv = (lig < 4) ? __ldcs(row + 96 + lig)
                                  : make_float4(1.f, 1.f, 1.f, 1.f);
            if (it & 1) buf1 = nv; else buf0 = nv;
        }
        if (it == 12 && lig >= 4) a4 = make_float4(1.f, 1.f, 1.f, 1.f);

        float a0 = fmaxf(a4.x, EPSc);
        float a1 = fmaxf(a4.y, EPSc);
        float a2 = fmaxf(a4.z, EPSc);
        float a3 = fmaxf(a4.w, EPSc);
        float p0 = fast_lg2(a0);
        float p1 = fast_lg2(a1);
        float p2 = fast_lg2(a2);
        float p3 = fast_lg2(a3);
        E2 += a0 * p0;
        E2 += a1 * p1;
        E2 += a2 * p2;
        E2 += a3 * p3;

        int seg_lo = it * 32;              // l range of this iteration per group
        bool inband = (seg_lo <= band_hi) && (seg_lo + 31 >= band_lo);
        if (__any_sync(0xffffffffu, inband)) {
            int j = it * 8 + lig;
            int l0 = j * 4;
            bool jv = (it < 12) || (lig < 4);
            float u0 = ((float)l0 - ep) * K2;
            float u1 = u0 + K2;
            float u2 = u1 + K2;
            float u3 = u2 + K2;
            float h0 = -u0 * u0;
            float h1 = -u1 * u1;
            float h2 = -u2 * u2;
            float h3 = -u3 * u3;
            bool m = inband & jv;
            float g0 = (m && l0 + 0 < Lb) ? fast_ex2(h0) : 0.f;
            float g1 = (m && l0 + 1 < Lb) ? fast_ex2(h1) : 0.f;
            float g2 = (m && l0 + 2 < Lb) ? fast_ex2(h2) : 0.f;
            float g3 = (m && l0 + 3 < Lb) ? fast_ex2(h3) : 0.f;
            sg += (g0 + g1) + (g2 + g3);
            A2 += g0 * (h0 - p0);
            A2 += g1 * (h1 - p1);
            A2 += g2 * (h2 - p2);
            A2 += g3 * (h3 - p3);
        }
    }

    // row reduction within each 8-lane group (3 steps serve all 4 rows)
    sg += __shfl_xor_sync(0xffffffffu, sg, 1);
    sg += __shfl_xor_sync(0xffffffffu, sg, 2);
    sg += __shfl_xor_sync(0xffffffffu, sg, 4);
    A2 += __shfl_xor_sync(0xffffffffu, A2, 1);
    A2 += __shfl_xor_sync(0xffffffffu, A2, 2);
    A2 += __shfl_xor_sync(0xffffffffu, A2, 4);
    E2 += __shfl_xor_sync(0xffffffffu, E2, 1);
    E2 += __shfl_xor_sync(0xffffffffu, E2, 2);
    E2 += __shfl_xor_sync(0xffffffffu, E2, 4);

    float kl = 0.f, en = 0.f;
    if (lig == 0) {
        float S = sg + EPSc;
        float lnS = LN2f * fast_lg2(S);
        kl = (LN2f * A2 - sg * lnS) / S;
        en = LN2f * E2;
    }
    kl += __shfl_xor_sync(0xffffffffu, kl, 8);
    kl += __shfl_xor_sync(0xffffffffu, kl, 16);
    en += __shfl_xor_sync(0xffffffffu, en, 8);
    en += __shfl_xor_sync(0xffffffffu, en, 16);

    if (lane == 0) { sred[wid] = kl; sred[8 + wid] = en; }
    __syncthreads();
    if (wid == 0) {
        float k = (lane < 8) ? sred[lane] : 0.f;
        float e = (lane < 8) ? sred[8 + lane] : 0.f;
        k = warp_sum(k);
        e = warp_sum(e);
        if (lane == 0) {
            atomicAdd(&g_acc[3], (double)k);
            atomicAdd(&g_acc[4], (double)e);
        }
    }
}

// ---------------- mel L1 losses (4x unrolled grid-stride, streaming) -------
#define N_MEL 1600

__device__ __forceinline__ void mel_work(int mid,
                                         const float4* __restrict__ post,
                                         const float4* __restrict__ out,
                                         const float4* __restrict__ tgt,
                                         const int* __restrict__ mel_len,
                                         float* sred) {
    const int n4 = Bc * Tc * Mc / 4;  // 2,048,000
    const int stride = N_MEL * 256;
    float s1 = 0.f, s2 = 0.f;
    for (int i = mid * 256 + threadIdx.x; i < n4; i += 4 * stride) {
#pragma unroll
        for (int k = 0; k < 4; k++) {
            int idx = i + k * stride;
            if (idx < n4) {
                int rowi = idx / (Mc / 4);
                int b = rowi / Tc;
                int t = rowi - b * Tc;
                if (t < __ldg(&mel_len[b])) {
                    float4 o = __ldcs(out + idx);
                    float4 p = __ldcs(post + idx);
                    float4 g = __ldcs(tgt + idx);
                    s1 += (fabsf(o.x - g.x) + fabsf(o.y - g.y)) + (fabsf(o.z - g.z) + fabsf(o.w - g.w));
                    s2 += (fabsf(p.x - g.x) + fabsf(p.y - g.y)) + (fabsf(p.z - g.z) + fabsf(p.w - g.w));
                }
            }
        }
    }
    int lane = threadIdx.x & 31, wid = threadIdx.x >> 5;
    s1 = warp_sum(s1);
    s2 = warp_sum(s2);
    if (lane == 0) { sred[wid] = s1; sred[8 + wid] = s2; }
    __syncthreads();
    if (wid == 0) {
        float a = (lane < 8) ? sred[lane] : 0.f;
        float c = (lane < 8) ? sred[8 + lane] : 0.f;
        a = warp_sum(a);
        c = warp_sum(c);
        if (lane == 0) {
            atomicAdd(&g_acc[0], (double)a);
            atomicAdd(&g_acc[1], (double)c);
        }
    }
}

// ---------------- gate BCE-with-logits -------------------------------------
#define N_GATE 32

__device__ __forceinline__ void gate_work(int gid,
                                          const float* __restrict__ x,
                                          const float* __restrict__ z,
                                          float* sred) {
    const int n = Bc * Tc;
    int stride = N_GATE * 256;
    float s = 0.f;
    for (int i = gid * 256 + threadIdx.x; i < n; i += stride) {
        float xi = __ldcs(x + i), zi = __ldcs(z + i);
        s += fmaxf(xi, 0.f) - xi * zi + log1pf(__expf(-fabsf(xi)));
    }
    int lane = threadIdx.x & 31, wid = threadIdx.x >> 5;
    s = warp_sum(s);
    if (lane == 0) sred[wid] = s;
    __syncthreads();
    if (wid == 0) {
        float a = (lane < 8) ? sred[lane] : 0.f;
        a = warp_sum(a);
        if (lane == 0) atomicAdd(&g_acc[2], (double)a);
    }
}

// ---------------- fused kernel ---------------------------------------------
// bid < 5600:  q=bid/14, r=bid%14;  r<10  -> attn id q*10+r     ([0,4000))
//                                   r>=10 -> mel id q*4+(r-10)  ([0,1600))
// bid >= 5600: gate block ([0,32))
#define GRID_TOTAL (5600 + N_GATE)

__global__ void __launch_bounds__(256)
fused_kernel(const float4* __restrict__ post,
             const float4* __restrict__ out,
             const float*  __restrict__ gate_x,
             const float4* __restrict__ attn,
             const float4* __restrict__ tgt,
             const float*  __restrict__ gate_z,
             const int* __restrict__ mel_len,
             const int* __restrict__ text_len) {
    __shared__ float sred[16];
    int bid = blockIdx.x;
    if (bid >= 5600) {
        gate_work(bid - 5600, gate_x, gate_z, sred);
        return;
    }
    int q = bid / 14;
    int r = bid - 14 * q;
    if (r < 10) {
        attn_work(q * 10 + r, attn, text_len, sred);
    } else {
        mel_work(q * 4 + (r - 10), post, out, tgt, mel_len, sred);
    }
}

// ---------------- finalize (one warp, parallel mel_len sum) ----------------
__global__ void final_kernel(const int* __restrict__ mel_len,
                             float* __restrict__ outp) {
    int lane = threadIdx.x & 31;
    // parallel sum of mel_len (64 ints over 32 lanes)
    int ml = __ldg(&mel_len[lane]) + __ldg(&mel_len[lane + 32]);
    ml += __shfl_xor_sync(0xffffffffu, ml, 16);
    ml += __shfl_xor_sync(0xffffffffu, ml, 8);
    ml += __shfl_xor_sync(0xffffffffu, ml, 4);
    ml += __shfl_xor_sync(0xffffffffu, ml, 2);
    ml += __shfl_xor_sync(0xffffffffu, ml, 1);

    if (lane == 0) {
        double nvalid = (double)ml * (double)Mc;

        double loss_mel = (g_acc[0] + g_acc[1]) / nvalid;
        double loss_gate = g_acc[2] / (double)(Bc * Tc);
        double kl = g_acc[3] / (double)Bc / (double)Tc;
        if (kl > 150.0) kl = 150.0;
        double ent = -g_acc[4] / (double)(Bc * Tc);
        double ratio = ent / 3.5;
        if (ratio < 0.0) ratio = 0.0;
        double w;
        if (ent <= 3.5) {
            w = ratio > 0.2 ? ratio : 0.2;
        } else {
            w = 1.0;
        }
        double total = loss_mel + loss_gate + w * kl;
        outp[0] = (float)total;
        outp[1] = (float)loss_mel;
        outp[2] = (float)loss_gate;
        outp[3] = (float)kl;

        // reset for the next (replayed) invocation
        g_acc[0] = 0.0; g_acc[1] = 0.0; g_acc[2] = 0.0;
        g_acc[3] = 0.0; g_acc[4] = 0.0;
    }
}

extern "C" void kernel_launch(void* const* d_in, const int* in_sizes, int n_in,
                              void* d_out, int out_size) {
    const float* mel_out_postnet = (const float*)d_in[0];
    const float* mel_out         = (const float*)d_in[1];
    const float* gate_out        = (const float*)d_in[2];
    const float* alignments      = (const float*)d_in[3];
    const float* mel_target      = (const float*)d_in[4];
    const float* gate_target     = (const float*)d_in[5];
    const int*   mel_lengths     = (const int*)d_in[6];
    const int*   text_lengths    = (const int*)d_in[7];
    float* outp = (float*)d_out;

    fused_kernel<<<GRID_TOTAL, 256>>>((const float4*)mel_out_postnet,
                                      (const float4*)mel_out,
                                      gate_out,
                                      (const float4*)alignments,
                                      (const float4*)mel_target,
                                      gate_target,
                                      mel_lengths, text_lengths);
    final_kernel<<<1, 32>>>(mel_lengths, outp);
    (void)in_sizes; (void)n_in; (void)out_size;
}

// round 16
// speedup vs baseline: 1.1517x; 1.0285x over previous
#include <cuda_runtime.h>

#define Bc 64
#define Tc 2000
#define Lc 400
#define Mc 80
#define EPSc 1e-8f
#define LN2f 0.69314718055994531f
// sqrt(0.5 * log2(e)) — so that 2^{-((l-ep)*K2)^2} = e^{-z^2/2}, K2=SQHL2E/sigma
#define SQHL2E 0.84932180028801905f

// accumulators: 0=s1(mel1), 1=s2(mel2), 2=gate, 3=kl_sum, 4=ent_sum(Σ p*logp)
// Zero at module load; final_kernel re-zeros after use (graph-replay safe).
__device__ double g_acc[5];

__device__ __forceinline__ float fast_lg2(float x) {
    float r;
    asm("lg2.approx.f32 %0, %1;" : "=f"(r) : "f"(x));
    return r;
}
__device__ __forceinline__ float fast_ex2(float x) {
    float r;
    asm("ex2.approx.f32 %0, %1;" : "=f"(r) : "f"(x));
    return r;
}

__device__ __forceinline__ float warp_sum(float v) {
    v += __shfl_xor_sync(0xffffffffu, v, 16);
    v += __shfl_xor_sync(0xffffffffu, v, 8);
    v += __shfl_xor_sync(0xffffffffu, v, 4);
    v += __shfl_xor_sync(0xffffffffu, v, 2);
    v += __shfl_xor_sync(0xffffffffu, v, 1);
    return v;
}

// ---------------- attn: 4 rows per warp, 8 lanes per row, depth-2 pipeline -
__device__ __forceinline__ void attn_work(int aid, const float4* __restrict__ attn,
                                          const int* __restrict__ text_len,
                                          float* sred) {
    int lane = threadIdx.x & 31, wid = threadIdx.x >> 5;
    int lig = lane & 7;           // lane in 8-lane group
    int grp = lane >> 3;          // group 0..3
    int rowid = (aid * 8 + wid) * 4 + grp;          // [0, 128000)
    int b = (int)((unsigned)rowid / (unsigned)Tc);
    int t = rowid - b * Tc;

    int Lb = __ldg(&text_len[b]);
    float sigma = fminf(fmaxf((float)Lb * 0.05f, 3.0f), 10.0f);
    int ep_i = (t * Lb) / Tc;
    if (ep_i > Lb - 1) ep_i = Lb - 1;
    float ep = (float)ep_i;
    float K2 = SQHL2E / sigma;
    int band_lo = ep_i - 67, band_hi = ep_i + 67;

    const float4* row = attn + rowid * (Lc / 4);

    float E2 = 0.f, sg = 0.f, A2 = 0.f;
    // depth-2 register double-buffer (evict-first streaming loads)
    float4 buf0 = __ldcs(row + lig);          // it=0
    float4 buf1 = __ldcs(row + 8 + lig);      // it=1
#pragma unroll
    for (int it = 0; it < 13; it++) {
        float4 a4 = (it & 1) ? buf1 : buf0;
        // prefetch it+2
        if (it + 2 <= 11) {
            float4 nv = __ldcs(row + (it + 2) * 8 + lig);
            if (it & 1) buf1 = nv; else buf0 = nv;
        } else if (it + 2 == 12) {
            float4 nv = (lig < 4) ? __ldcs(row + 96 + lig)
                                  : make_float4(1.f, 1.f, 1.f, 1.f);
            if (it & 1) buf1 = nv; else buf0 = nv;
        }
        if (it == 12 && lig >= 4) a4 = make_float4(1.f, 1.f, 1.f, 1.f);

        float a0 = fmaxf(a4.x, EPSc);
        float a1 = fmaxf(a4.y, EPSc);
        float a2 = fmaxf(a4.z, EPSc);
        float a3 = fmaxf(a4.w, EPSc);
        float p0 = fast_lg2(a0);
        float p1 = fast_lg2(a1);
        float p2 = fast_lg2(a2);
        float p3 = fast_lg2(a3);
        E2 += a0 * p0;
        E2 += a1 * p1;
        E2 += a2 * p2;
        E2 += a3 * p3;

        int seg_lo = it * 32;              // l range of this iteration per group
        bool inband = (seg_lo <= band_hi) && (seg_lo + 31 >= band_lo);
        if (__any_sync(0xffffffffu, inband)) {
            int j = it * 8 + lig;
            int l0 = j * 4;
            bool jv = (it < 12) || (lig < 4);
            float u0 = ((float)l0 - ep) * K2;
            float u1 = u0 + K2;
            float u2 = u1 + K2;
            float u3 = u2 + K2;
            float h0 = -u0 * u0;
            float h1 = -u1 * u1;
            float h2 = -u2 * u2;
            float h3 = -u3 * u3;
            bool m = inband & jv;
            float g0 = (m && l0 + 0 < Lb) ? fast_ex2(h0) : 0.f;
            float g1 = (m && l0 + 1 < Lb) ? fast_ex2(h1) : 0.f;
            float g2 = (m && l0 + 2 < Lb) ? fast_ex2(h2) : 0.f;
            float g3 = (m && l0 + 3 < Lb) ? fast_ex2(h3) : 0.f;
            sg += (g0 + g1) + (g2 + g3);
            A2 += g0 * (h0 - p0);
            A2 += g1 * (h1 - p1);
            A2 += g2 * (h2 - p2);
            A2 += g3 * (h3 - p3);
        }
    }

    // row reduction within each 8-lane group (3 steps serve all 4 rows)
    sg += __shfl_xor_sync(0xffffffffu, sg, 1);
    sg += __shfl_xor_sync(0xffffffffu, sg, 2);
    sg += __shfl_xor_sync(0xffffffffu, sg, 4);
    A2 += __shfl_xor_sync(0xffffffffu, A2, 1);
    A2 += __shfl_xor_sync(0xffffffffu, A2, 2);
    A2 += __shfl_xor_sync(0xffffffffu, A2, 4);
    E2 += __shfl_xor_sync(0xffffffffu, E2, 1);
    E2 += __shfl_xor_sync(0xffffffffu, E2, 2);
    E2 += __shfl_xor_sync(0xffffffffu, E2, 4);

    float kl = 0.f, en = 0.f;
    if (lig == 0) {
        float S = sg + EPSc;
        float lnS = LN2f * fast_lg2(S);
        kl = (LN2f * A2 - sg * lnS) / S;
        en = LN2f * E2;
    }
    kl += __shfl_xor_sync(0xffffffffu, kl, 8);
    kl += __shfl_xor_sync(0xffffffffu, kl, 16);
    en += __shfl_xor_sync(0xffffffffu, en, 8);
    en += __shfl_xor_sync(0xffffffffu, en, 16);

    if (lane == 0) { sred[wid] = kl; sred[8 + wid] = en; }
    __syncthreads();
    if (wid == 0) {
        float k = (lane < 8) ? sred[lane] : 0.f;
        float e = (lane < 8) ? sred[8 + lane] : 0.f;
        k = warp_sum(k);
        e = warp_sum(e);
        if (lane == 0) {
            atomicAdd(&g_acc[3], (double)k);
            atomicAdd(&g_acc[4], (double)e);
        }
    }
}

// ---------------- mel L1 losses (4x unrolled grid-stride, streaming) -------
#define N_MEL 1600

__device__ __forceinline__ void mel_work(int mid,
                                         const float4* __restrict__ post,
                                         const float4* __restrict__ out,
                                         const float4* __restrict__ tgt,
                                         const int* __restrict__ mel_len,
                                         float* sred) {
    const int n4 = Bc * Tc * Mc / 4;  // 2,048,000
    const int stride = N_MEL * 256;
    float s1 = 0.f, s2 = 0.f;
    for (int i = mid * 256 + threadIdx.x; i < n4; i += 4 * stride) {
#pragma unroll
        for (int k = 0; k < 4; k++) {
            int idx = i + k * stride;
            if (idx < n4) {
                int rowi = idx / (Mc / 4);
                int b = rowi / Tc;
                int t = rowi - b * Tc;
                if (t < __ldg(&mel_len[b])) {
                    float4 o = __ldcs(out + idx);
                    float4 p = __ldcs(post + idx);
                    float4 g = __ldcs(tgt + idx);
                    s1 += (fabsf(o.x - g.x) + fabsf(o.y - g.y)) + (fabsf(o.z - g.z) + fabsf(o.w - g.w));
                    s2 += (fabsf(p.x - g.x) + fabsf(p.y - g.y)) + (fabsf(p.z - g.z) + fabsf(p.w - g.w));
                }
            }
        }
    }
    int lane = threadIdx.x & 31, wid = threadIdx.x >> 5;
    s1 = warp_sum(s1);
    s2 = warp_sum(s2);
    if (lane == 0) { sred[wid] = s1; sred[8 + wid] = s2; }
    __syncthreads();
    if (wid == 0) {
        float a = (lane < 8) ? sred[lane] : 0.f;
        float c = (lane < 8) ? sred[8 + lane] : 0.f;
        a = warp_sum(a);
        c = warp_sum(c);
        if (lane == 0) {
            atomicAdd(&g_acc[0], (double)a);
            atomicAdd(&g_acc[1], (double)c);
        }
    }
}

// ---------------- gate BCE-with-logits -------------------------------------
#define N_GATE 32

__device__ __forceinline__ void gate_work(int gid,
                                          const float* __restrict__ x,
                                          const float* __restrict__ z,
                                          float* sred) {
    const int n = Bc * Tc;
    int stride = N_GATE * 256;
    float s = 0.f;
    for (int i = gid * 256 + threadIdx.x; i < n; i += stride) {
        float xi = __ldcs(x + i), zi = __ldcs(z + i);
        s += fmaxf(xi, 0.f) - xi * zi + log1pf(__expf(-fabsf(xi)));
    }
    int lane = threadIdx.x & 31, wid = threadIdx.x >> 5;
    s = warp_sum(s);
    if (lane == 0) sred[wid] = s;
    __syncthreads();
    if (wid == 0) {
        float a = (lane < 8) ? sred[lane] : 0.f;
        a = warp_sum(a);
        if (lane == 0) atomicAdd(&g_acc[2], (double)a);
    }
}

// ---------------- fused kernel ---------------------------------------------
// bid < 5600:  q=bid/14, r=bid%14;  r<10  -> attn id q*10+r     ([0,4000))
//                                   r>=10 -> mel id q*4+(r-10)  ([0,1600))
// bid >= 5600: gate block ([0,32))
#define GRID_TOTAL (5600 + N_GATE)

__global__ void __launch_bounds__(256)
fused_kernel(const float4* __restrict__ post,
             const float4* __restrict__ out,
             const float*  __restrict__ gate_x,
             const float4* __restrict__ attn,
             const float4* __restrict__ tgt,
             const float*  __restrict__ gate_z,
             const int* __restrict__ mel_len,
             const int* __restrict__ text_len) {
    __shared__ float sred[16];
    int bid = blockIdx.x;
    if (bid >= 5600) {
        gate_work(bid - 5600, gate_x, gate_z, sred);
        return;
    }
    int q = bid / 14;
    int r = bid - 14 * q;
    if (r < 10) {
        attn_work(q * 10 + r, attn, text_len, sred);
    } else {
        mel_work(q * 4 + (r - 10), post, out, tgt, mel_len, sred);
    }
}

// ---------------- finalize (PDL secondary; one warp) -----------------------
__global__ void final_kernel(const int* __restrict__ mel_len,
                             float* __restrict__ outp) {
    int lane = threadIdx.x & 31;
    // overlap these independent loads with the primary kernel's tail
    int ml = __ldg(&mel_len[lane]) + __ldg(&mel_len[lane + 32]);
    ml += __shfl_xor_sync(0xffffffffu, ml, 16);
    ml += __shfl_xor_sync(0xffffffffu, ml, 8);
    ml += __shfl_xor_sync(0xffffffffu, ml, 4);
    ml += __shfl_xor_sync(0xffffffffu, ml, 2);
    ml += __shfl_xor_sync(0xffffffffu, ml, 1);

    // wait for fused_kernel's grid to complete (memory made visible)
    cudaGridDependencySynchronize();

    if (lane == 0) {
        double nvalid = (double)ml * (double)Mc;

        double loss_mel = (g_acc[0] + g_acc[1]) / nvalid;
        double loss_gate = g_acc[2] / (double)(Bc * Tc);
        double kl = g_acc[3] / (double)Bc / (double)Tc;
        if (kl > 150.0) kl = 150.0;
        double ent = -g_acc[4] / (double)(Bc * Tc);
        double ratio = ent / 3.5;
        if (ratio < 0.0) ratio = 0.0;
        double w;
        if (ent <= 3.5) {
            w = ratio > 0.2 ? ratio : 0.2;
        } else {
            w = 1.0;
        }
        double total = loss_mel + loss_gate + w * kl;
        outp[0] = (float)total;
        outp[1] = (float)loss_mel;
        outp[2] = (float)loss_gate;
        outp[3] = (float)kl;

        // reset for the next (replayed) invocation
        g_acc[0] = 0.0; g_acc[1] = 0.0; g_acc[2] = 0.0;
        g_acc[3] = 0.0; g_acc[4] = 0.0;
    }
}

extern "C" void kernel_launch(void* const* d_in, const int* in_sizes, int n_in,
                              void* d_out, int out_size) {
    const float* mel_out_postnet = (const float*)d_in[0];
    const float* mel_out         = (const float*)d_in[1];
    const float* gate_out        = (const float*)d_in[2];
    const float* alignments      = (const float*)d_in[3];
    const float* mel_target      = (const float*)d_in[4];
    const float* gate_target     = (const float*)d_in[5];
    const int*   mel_lengths     = (const int*)d_in[6];
    const int*   text_lengths    = (const int*)d_in[7];
    float* outp = (float*)d_out;

    fused_kernel<<<GRID_TOTAL, 256>>>((const float4*)mel_out_postnet,
                                      (const float4*)mel_out,
                                      gate_out,
                                      (const float4*)alignments,
                                      (const float4*)mel_target,
                                      gate_target,
                                      mel_lengths, text_lengths);

    // Programmatic dependent launch: final_kernel goes resident while
    // fused_kernel drains; cudaGridDependencySynchronize() inside provides
    // the ordering on g_acc.
    cudaLaunchConfig_t cfg = {};
    cfg.gridDim = dim3(1, 1, 1);
    cfg.blockDim = dim3(32, 1, 1);
    cfg.dynamicSmemBytes = 0;
    cfg.stream = 0;
    cudaLaunchAttribute attrs[1];
    attrs[0].id = cudaLaunchAttributeProgrammaticStreamSerialization;
    attrs[0].val.programmaticStreamSerializationAllowed = 1;
    cfg.attrs = attrs;
    cfg.numAttrs = 1;
    cudaLaunchKernelEx(&cfg, final_kernel, mel_lengths, outp);

    (void)in_sizes; (void)n_in; (void)out_size;
}